// round 1
// baseline (speedup 1.0000x reference)
#include <cuda_runtime.h>
#include <cuda_bf16.h>
#include <math.h>

// Problem constants
#define Rr   16
#define Cc   256
#define Bb   12
#define Ee   768
#define Hh   12
#define Dd   64
#define RD   (Rr*Dd)          // 1024
#define NTOK (Rr*Cc*Bb)       // 49152
#define NB   32               // NUM_BUCKETS
#define SCALING 0.03125f      // D^-0.5 / sqrt(R) = 0.125/4

// Scratch (__device__ globals; no allocation allowed)
__device__ float g_q[(size_t)Bb*Hh*Cc*RD];     // (n,h,i,rd)   151MB
__device__ float g_k[(size_t)Bb*Hh*Cc*RD];     // (n,h,j,rd)
__device__ float g_v[(size_t)Bb*Hh*Cc*RD];     // (n,h,j,rd)
__device__ float g_s[(size_t)Hh*Bb*Cc*Cc];     // (h,n,i,j)    38MB
__device__ float g_ctx[(size_t)NTOK*Ee];       // (r,i,n, h*64+d) 151MB

// ---------------------------------------------------------------------------
// T5 relative-position bucket (distances are all >= 0 here)
// ---------------------------------------------------------------------------
__device__ __forceinline__ int rel_bucket(int dist) {
    if (dist < 16) return dist;
    float nf = fmaxf((float)dist, 1.0f);
    // matches: log(n/16) / np.log(50000/16) * 15, trunc toward zero
    float v = logf(nf * (1.0f/16.0f)) / 8.047189562170502f * 15.0f;
    int b = 16 + (int)v;
    return b < 31 ? b : 31;
}

// ---------------------------------------------------------------------------
// GEMM tile config: 128x128 block, BK=8, 256 threads, 8x8 per thread
// (two 4x4 quads at +0 / +64 in each dim for conflict-light smem reads)
// ---------------------------------------------------------------------------

// Kernel 1: fused Q/K/V projection + scatter.
// C[m][e] = sum_k x[m][k] * W[e][k] + bias[e]   (NT)
__global__ __launch_bounds__(256) void proj_qkv_kernel(
    const float* __restrict__ x,
    const float* __restrict__ Wq, const float* __restrict__ bq,
    const float* __restrict__ Wk, const float* __restrict__ bk,
    const float* __restrict__ Wv, const float* __restrict__ bv)
{
    __shared__ float As[8][128];
    __shared__ float Bs[8][128];

    const int z  = blockIdx.z;
    const float* W    = (z == 0) ? Wq : (z == 1) ? Wk : Wv;
    const float* bias = (z == 0) ? bq : (z == 1) ? bk : bv;
    float*       dst  = (z == 0) ? g_q : (z == 1) ? g_k : g_v;
    const float  scale = (z == 0) ? SCALING : 1.0f;

    const int m0 = blockIdx.y * 128;
    const int n0 = blockIdx.x * 128;
    const int tid = threadIdx.x;
    const int tx = tid & 15, ty = tid >> 4;
    const int lrow = tid >> 1, lcol = (tid & 1) * 4;

    float acc[8][8];
    #pragma unroll
    for (int i = 0; i < 8; i++)
        #pragma unroll
        for (int j = 0; j < 8; j++) acc[i][j] = 0.0f;

    const float* Ag = x + (size_t)(m0 + lrow) * Ee + lcol;
    const float* Bg = W + (size_t)(n0 + lrow) * Ee + lcol;

    for (int k0 = 0; k0 < Ee; k0 += 8) {
        float4 av = *(const float4*)(Ag + k0);
        float4 bv4 = *(const float4*)(Bg + k0);
        __syncthreads();
        As[lcol+0][lrow] = av.x;  As[lcol+1][lrow] = av.y;
        As[lcol+2][lrow] = av.z;  As[lcol+3][lrow] = av.w;
        Bs[lcol+0][lrow] = bv4.x; Bs[lcol+1][lrow] = bv4.y;
        Bs[lcol+2][lrow] = bv4.z; Bs[lcol+3][lrow] = bv4.w;
        __syncthreads();
        #pragma unroll
        for (int kk = 0; kk < 8; kk++) {
            float4 a0 = *(const float4*)&As[kk][ty*4];
            float4 a1 = *(const float4*)&As[kk][64 + ty*4];
            float4 b0 = *(const float4*)&Bs[kk][tx*4];
            float4 b1 = *(const float4*)&Bs[kk][64 + tx*4];
            float a[8] = {a0.x,a0.y,a0.z,a0.w,a1.x,a1.y,a1.z,a1.w};
            float b[8] = {b0.x,b0.y,b0.z,b0.w,b1.x,b1.y,b1.z,b1.w};
            #pragma unroll
            for (int i = 0; i < 8; i++)
                #pragma unroll
                for (int j = 0; j < 8; j++) acc[i][j] += a[i]*b[j];
        }
    }

    // Epilogue: scatter into (n, h, i, r*64+d), apply bias (+ scaling for q)
    #pragma unroll
    for (int ii = 0; ii < 8; ii++) {
        int mrel = (ii < 4) ? (ty*4 + ii) : (64 + ty*4 + ii - 4);
        int m = m0 + mrel;
        int r   = m / (Cc*Bb);
        int rem = m - r * (Cc*Bb);
        int ci  = rem / Bb;
        int n   = rem - ci * Bb;
        #pragma unroll
        for (int jj = 0; jj < 8; jj++) {
            int erel = (jj < 4) ? (tx*4 + jj) : (64 + tx*4 + jj - 4);
            int e = n0 + erel;
            int h = e >> 6, d = e & 63;
            float vv = (acc[ii][jj] + __ldg(&bias[e])) * scale;
            dst[(((size_t)n*Hh + h)*Cc + ci)*RD + r*Dd + d] = vv;
        }
    }
}

// Kernel 2: scores S[h,n,i,j] = Q_nh[i,:] . K_nh[j,:] + bias   (NT, K=1024)
__global__ __launch_bounds__(256) void scores_kernel(
    const int* __restrict__ distances, const float* __restrict__ rel_bias)
{
    __shared__ float As[8][128];
    __shared__ float Bs[8][128];

    const int z = blockIdx.z;           // z = h*Bb + n
    const int h = z / Bb, n = z % Bb;
    const size_t base = ((size_t)n*Hh + h) * Cc * RD;

    const int m0 = blockIdx.y * 128;
    const int n0 = blockIdx.x * 128;
    const int tid = threadIdx.x;
    const int tx = tid & 15, ty = tid >> 4;
    const int lrow = tid >> 1, lcol = (tid & 1) * 4;

    float acc[8][8];
    #pragma unroll
    for (int i = 0; i < 8; i++)
        #pragma unroll
        for (int j = 0; j < 8; j++) acc[i][j] = 0.0f;

    const float* Ag = g_q + base + (size_t)(m0 + lrow) * RD + lcol;
    const float* Bg = g_k + base + (size_t)(n0 + lrow) * RD + lcol;

    for (int k0 = 0; k0 < RD; k0 += 8) {
        float4 av = *(const float4*)(Ag + k0);
        float4 bv4 = *(const float4*)(Bg + k0);
        __syncthreads();
        As[lcol+0][lrow] = av.x;  As[lcol+1][lrow] = av.y;
        As[lcol+2][lrow] = av.z;  As[lcol+3][lrow] = av.w;
        Bs[lcol+0][lrow] = bv4.x; Bs[lcol+1][lrow] = bv4.y;
        Bs[lcol+2][lrow] = bv4.z; Bs[lcol+3][lrow] = bv4.w;
        __syncthreads();
        #pragma unroll
        for (int kk = 0; kk < 8; kk++) {
            float4 a0 = *(const float4*)&As[kk][ty*4];
            float4 a1 = *(const float4*)&As[kk][64 + ty*4];
            float4 b0 = *(const float4*)&Bs[kk][tx*4];
            float4 b1 = *(const float4*)&Bs[kk][64 + tx*4];
            float a[8] = {a0.x,a0.y,a0.z,a0.w,a1.x,a1.y,a1.z,a1.w};
            float b[8] = {b0.x,b0.y,b0.z,b0.w,b1.x,b1.y,b1.z,b1.w};
            #pragma unroll
            for (int i = 0; i < 8; i++)
                #pragma unroll
                for (int j = 0; j < 8; j++) acc[i][j] += a[i]*b[j];
        }
    }

    float* Sdst = g_s + (size_t)z * Cc * Cc;
    #pragma unroll
    for (int ii = 0; ii < 8; ii++) {
        int i = m0 + ((ii < 4) ? (ty*4 + ii) : (64 + ty*4 + ii - 4));
        #pragma unroll
        for (int jj = 0; jj < 8; jj++) {
            int j = n0 + ((jj < 4) ? (tx*4 + jj) : (64 + tx*4 + jj - 4));
            // positional add quirk (B==H): distances indexed by h, bias column by n
            int dist = __ldg(&distances[((size_t)h*Cc + i)*Cc + j]);
            int bu = rel_bucket(dist);
            float bias = __ldg(&rel_bias[bu*Hh + n]);
            Sdst[(size_t)i*Cc + j] = acc[ii][jj] + bias;
        }
    }
}

// Kernel 3: in-place row softmax over last dim (256) of g_s
__global__ __launch_bounds__(256) void softmax_kernel()
{
    float* p = g_s + (size_t)blockIdx.x * Cc;
    const int t = threadIdx.x;
    const int lane = t & 31, w = t >> 5;
    __shared__ float red[8];

    float v = p[t];

    float m = v;
    #pragma unroll
    for (int o = 16; o > 0; o >>= 1)
        m = fmaxf(m, __shfl_xor_sync(0xffffffffu, m, o));
    if (lane == 0) red[w] = m;
    __syncthreads();
    if (w == 0) {
        float mm = red[lane & 7];
        #pragma unroll
        for (int o = 4; o > 0; o >>= 1)
            mm = fmaxf(mm, __shfl_xor_sync(0xffffffffu, mm, o));
        if (lane == 0) red[0] = mm;
    }
    __syncthreads();
    m = red[0];
    __syncthreads();

    float e = expf(v - m);
    float s = e;
    #pragma unroll
    for (int o = 16; o > 0; o >>= 1)
        s += __shfl_xor_sync(0xffffffffu, s, o);
    if (lane == 0) red[w] = s;
    __syncthreads();
    if (w == 0) {
        float ss = red[lane & 7];
        #pragma unroll
        for (int o = 4; o > 0; o >>= 1)
            ss += __shfl_xor_sync(0xffffffffu, ss, o);
        if (lane == 0) red[0] = ss;
    }
    __syncthreads();
    float denom = red[0];

    p[t] = e / denom;
}

// Kernel 4: ctx_nh[i, rd] = sum_j P_nh[i,j] * V_nh[j, rd]   (NN, K=256)
__global__ __launch_bounds__(256) void ctx_kernel()
{
    __shared__ float As[8][128];
    __shared__ float Bs[8][128];

    const int z = blockIdx.z;           // z = h*Bb + n
    const int h = z / Bb, n = z % Bb;

    const int m0 = blockIdx.y * 128;    // i
    const int n0 = blockIdx.x * 128;    // rd
    const int tid = threadIdx.x;
    const int tx = tid & 15, ty = tid >> 4;
    const int lrow = tid >> 1, lcol = (tid & 1) * 4;     // A-tile (transposed store)
    const int bkrow = tid >> 5, bcol = (tid & 31) * 4;   // B-tile (direct store)

    float acc[8][8];
    #pragma unroll
    for (int i = 0; i < 8; i++)
        #pragma unroll
        for (int j = 0; j < 8; j++) acc[i][j] = 0.0f;

    const float* Ag = g_s + (size_t)z * Cc * Cc + (size_t)(m0 + lrow) * Cc + lcol;
    const float* Bg = g_v + ((size_t)n*Hh + h) * Cc * RD;   // (j, rd), ld = 1024

    for (int k0 = 0; k0 < Cc; k0 += 8) {
        float4 av = *(const float4*)(Ag + k0);
        float4 bv4 = *(const float4*)(Bg + (size_t)(k0 + bkrow) * RD + n0 + bcol);
        __syncthreads();
        As[lcol+0][lrow] = av.x; As[lcol+1][lrow] = av.y;
        As[lcol+2][lrow] = av.z; As[lcol+3][lrow] = av.w;
        *(float4*)&Bs[bkrow][bcol] = bv4;
        __syncthreads();
        #pragma unroll
        for (int kk = 0; kk < 8; kk++) {
            float4 a0 = *(const float4*)&As[kk][ty*4];
            float4 a1 = *(const float4*)&As[kk][64 + ty*4];
            float4 b0 = *(const float4*)&Bs[kk][tx*4];
            float4 b1 = *(const float4*)&Bs[kk][64 + tx*4];
            float a[8] = {a0.x,a0.y,a0.z,a0.w,a1.x,a1.y,a1.z,a1.w};
            float b[8] = {b0.x,b0.y,b0.z,b0.w,b1.x,b1.y,b1.z,b1.w};
            #pragma unroll
            for (int i = 0; i < 8; i++)
                #pragma unroll
                for (int j = 0; j < 8; j++) acc[i][j] += a[i]*b[j];
        }
    }

    // Scatter: ctx[r, i(ci), n, h*64+d]
    #pragma unroll
    for (int ii = 0; ii < 8; ii++) {
        int i = m0 + ((ii < 4) ? (ty*4 + ii) : (64 + ty*4 + ii - 4));
        #pragma unroll
        for (int jj = 0; jj < 8; jj++) {
            int rd = n0 + ((jj < 4) ? (tx*4 + jj) : (64 + tx*4 + jj - 4));
            int r = rd >> 6, d = rd & 63;
            g_ctx[(((size_t)r*Cc + i)*Bb + n)*Ee + h*Dd + d] = acc[ii][jj];
        }
    }
}

// Kernel 5: out[m][e] = sum_k ctx[m][k] * Wo[e][k] + bo[e]   (NT)
__global__ __launch_bounds__(256) void outproj_kernel(
    const float* __restrict__ Wo, const float* __restrict__ bo,
    float* __restrict__ out)
{
    __shared__ float As[8][128];
    __shared__ float Bs[8][128];

    const int m0 = blockIdx.y * 128;
    const int n0 = blockIdx.x * 128;
    const int tid = threadIdx.x;
    const int tx = tid & 15, ty = tid >> 4;
    const int lrow = tid >> 1, lcol = (tid & 1) * 4;

    float acc[8][8];
    #pragma unroll
    for (int i = 0; i < 8; i++)
        #pragma unroll
        for (int j = 0; j < 8; j++) acc[i][j] = 0.0f;

    const float* Ag = g_ctx + (size_t)(m0 + lrow) * Ee + lcol;
    const float* Bg = Wo    + (size_t)(n0 + lrow) * Ee + lcol;

    for (int k0 = 0; k0 < Ee; k0 += 8) {
        float4 av = *(const float4*)(Ag + k0);
        float4 bv4 = *(const float4*)(Bg + k0);
        __syncthreads();
        As[lcol+0][lrow] = av.x;  As[lcol+1][lrow] = av.y;
        As[lcol+2][lrow] = av.z;  As[lcol+3][lrow] = av.w;
        Bs[lcol+0][lrow] = bv4.x; Bs[lcol+1][lrow] = bv4.y;
        Bs[lcol+2][lrow] = bv4.z; Bs[lcol+3][lrow] = bv4.w;
        __syncthreads();
        #pragma unroll
        for (int kk = 0; kk < 8; kk++) {
            float4 a0 = *(const float4*)&As[kk][ty*4];
            float4 a1 = *(const float4*)&As[kk][64 + ty*4];
            float4 b0 = *(const float4*)&Bs[kk][tx*4];
            float4 b1 = *(const float4*)&Bs[kk][64 + tx*4];
            float a[8] = {a0.x,a0.y,a0.z,a0.w,a1.x,a1.y,a1.z,a1.w};
            float b[8] = {b0.x,b0.y,b0.z,b0.w,b1.x,b1.y,b1.z,b1.w};
            #pragma unroll
            for (int i = 0; i < 8; i++)
                #pragma unroll
                for (int j = 0; j < 8; j++) acc[i][j] += a[i]*b[j];
        }
    }

    #pragma unroll
    for (int ii = 0; ii < 8; ii++) {
        int m = m0 + ((ii < 4) ? (ty*4 + ii) : (64 + ty*4 + ii - 4));
        #pragma unroll
        for (int jj = 0; jj < 8; jj++) {
            int e = n0 + ((jj < 4) ? (tx*4 + jj) : (64 + tx*4 + jj - 4));
            out[(size_t)m*Ee + e] = acc[ii][jj] + __ldg(&bo[e]);
        }
    }
}

// Kernel 6: copy probs (g_s already in (h,n,i,j) layout) into d_out tail
__global__ __launch_bounds__(256) void copy_probs_kernel(float* __restrict__ dst)
{
    size_t idx = (size_t)blockIdx.x * 256 + threadIdx.x;
    ((float4*)dst)[idx] = ((const float4*)g_s)[idx];
}

// ---------------------------------------------------------------------------
extern "C" void kernel_launch(void* const* d_in, const int* in_sizes, int n_in,
                              void* d_out, int out_size)
{
    const float* x         = (const float*)d_in[0];
    const int*   distances = (const int*)  d_in[1];
    const float* Wq = (const float*)d_in[2];
    const float* bq = (const float*)d_in[3];
    const float* Wk = (const float*)d_in[4];
    const float* bk = (const float*)d_in[5];
    const float* Wv = (const float*)d_in[6];
    const float* bv = (const float*)d_in[7];
    const float* Wo = (const float*)d_in[8];
    const float* bo = (const float*)d_in[9];
    const float* rel_bias = (const float*)d_in[10];
    float* out = (float*)d_out;

    dim3 blk(256);

    // 1. Q/K/V projections (N=49152 x E=768, K=768), z selects q/k/v
    proj_qkv_kernel<<<dim3(Ee/128, NTOK/128, 3), blk>>>(x, Wq, bq, Wk, bk, Wv, bv);

    // 2. Scores: per (h,n) 256x256, K=1024 (+ bucket bias)
    scores_kernel<<<dim3(2, 2, Hh*Bb), blk>>>(distances, rel_bias);

    // 3. Softmax over rows of g_s
    softmax_kernel<<<Hh*Bb*Cc, 256>>>();

    // 4. Context: per (h,n) 256x1024, K=256
    ctx_kernel<<<dim3(RD/128, 2, Hh*Bb), blk>>>();

    // 5. Output projection -> d_out[0 .. NTOK*Ee)
    outproj_kernel<<<dim3(Ee/128, NTOK/128), blk>>>(Wo, bo, out);

    // 6. probs -> d_out tail (if the harness expects the (out, probs) tuple)
    const size_t out_elems   = (size_t)NTOK * Ee;            // 37,748,736
    const size_t probs_elems = (size_t)Hh * Bb * Cc * Cc;    //  9,437,184
    if ((size_t)out_size >= out_elems + probs_elems) {
        copy_probs_kernel<<<(unsigned)(probs_elems / 4 / 256), blk>>>(out + out_elems);
    }
}